// round 10
// baseline (speedup 1.0000x reference)
#include <cuda_runtime.h>
#include <cuda_bf16.h>
#include <cstdint>

#define NN 200000
#define EE 400000
#define HH 128
#define GG 4096
#define LL 3

// ---------------- scratch (static __device__, allocation-free) ----------------
__device__ __align__(16) float g_h [(size_t)NN * HH];   // node features (residual)
__device__ __align__(16) float g_m [(size_t)NN * HH];   // per-layer linear output
__device__ __align__(16) float g_hn[(size_t)NN * HH];   // aggregated messages
__device__ __align__(16) __nv_bfloat16 g_wthi[4 * HH * HH];  // W^T hi, [w][n][k]
__device__ __align__(16) __nv_bfloat16 g_wtlo[4 * HH * HH];  // W^T lo
__device__ float  g_deg[NN];
__device__ int    g_icnt[NN];
__device__ int    g_off[NN + 1];
__device__ int    g_cur[NN];
__device__ int    g_src[EE];
__device__ float  g_nrm[EE];                            // dinv[src]*dinv[dst] per CSR slot
__device__ int    g_bsum[1024];
__device__ int    g_boff[1024];
__device__ double g_sum[HH];
__device__ double g_sumsq[HH];
__device__ __align__(16) float g_scale[HH];
__device__ __align__(16) float g_shift[HH];
__device__ __align__(16) float g_gsum[(size_t)GG * HH];
__device__ float g_gcnt[GG];
__device__ int   g_idx64;
__device__ int   g_bidx64;

// ---------------- helpers ----------------
__device__ __forceinline__ void split_bf(float v, unsigned short& hi, unsigned short& lo) {
    __nv_bfloat16 h = __float2bfloat16(v);
    __nv_bfloat16 l = __float2bfloat16(v - __bfloat162float(h));
    hi = *(unsigned short*)&h;
    lo = *(unsigned short*)&l;
}
__device__ __forceinline__ uint32_t pack_us(unsigned short a, unsigned short b) {
    return (uint32_t)a | ((uint32_t)b << 16);
}
__device__ __forceinline__ void mma_bf16(float* d, const uint32_t* a, uint32_t b0, uint32_t b1) {
    asm volatile(
        "mma.sync.aligned.m16n8k16.row.col.f32.bf16.bf16.f32 "
        "{%0,%1,%2,%3}, {%4,%5,%6,%7}, {%8,%9}, {%0,%1,%2,%3};"
        : "+f"(d[0]), "+f"(d[1]), "+f"(d[2]), "+f"(d[3])
        : "r"(a[0]), "r"(a[1]), "r"(a[2]), "r"(a[3]), "r"(b0), "r"(b1));
}

// ---------------- index width detection (bounds-safe for both widths) ----------------
__global__ void detect_kernel(const void* edge, const void* batch) {
    const int* we = (const int*)edge;
    const int* wb = (const int*)batch;
    int nz_e = 0, nz_b = 0;
    for (int i = 0; i < 64; i++) {
        nz_e |= we[1 + 2 * (i * (EE / 64))];
        nz_b |= wb[(NN - 1) - 2 * i];
    }
    g_idx64  = (nz_e == 0) ? 1 : 0;
    g_bidx64 = (nz_b == 0) ? 1 : 0;
}
__device__ __forceinline__ int ld_eidx(const void* p, int i) {
    return g_idx64 ? (int)((const long long*)p)[i] : ((const int*)p)[i];
}
__device__ __forceinline__ int ld_bidx(const void* p, int i) {
    return g_bidx64 ? (int)((const long long*)p)[i] : ((const int*)p)[i];
}

// ---------------- setup / degree / CSR ----------------
__global__ void setup_kernel() {
    int i = blockIdx.x * blockDim.x + threadIdx.x;
    if (i < NN) { g_icnt[i] = 0; g_cur[i] = 0; }
    if (i < GG * HH) g_gsum[i] = 0.0f;
    if (i < GG) g_gcnt[i] = 0.0f;
    if (i < HH) { g_sum[i] = 0.0; g_sumsq[i] = 0.0; }
}
__global__ void deg_kernel(const void* edge) {
    int e = blockIdx.x * blockDim.x + threadIdx.x;
    if (e < EE) atomicAdd(&g_icnt[ld_eidx(edge, EE + e)], 1);
}
// blocksum + dinv fused
__global__ __launch_bounds__(256) void blocksum_kernel() {
    __shared__ int sm[256];
    int t = threadIdx.x, i = blockIdx.x * 256 + t;
    int c = (i < NN) ? g_icnt[i] : 0;
    if (i < NN) g_deg[i] = rsqrtf((float)(c + 1));
    sm[t] = c;
    __syncthreads();
    for (int d = 128; d > 0; d >>= 1) { if (t < d) sm[t] += sm[t + d]; __syncthreads(); }
    if (t == 0) g_bsum[blockIdx.x] = sm[0];
}
__global__ __launch_bounds__(1024) void scanb_kernel(int nblocks) {
    __shared__ int sm[1024];
    int t = threadIdx.x;
    int v = (t < nblocks) ? g_bsum[t] : 0;
    sm[t] = v;
    __syncthreads();
    for (int d = 1; d < 1024; d <<= 1) {
        int add = (t >= d) ? sm[t - d] : 0;
        __syncthreads(); sm[t] += add; __syncthreads();
    }
    g_boff[t] = sm[t] - v;
}
__global__ __launch_bounds__(256) void offsets_kernel() {
    __shared__ int sm[256];
    int t = threadIdx.x, i = blockIdx.x * 256 + t;
    int c = (i < NN) ? g_icnt[i] : 0;
    sm[t] = c;
    __syncthreads();
    for (int d = 1; d < 256; d <<= 1) {
        int add = (t >= d) ? sm[t - d] : 0;
        __syncthreads(); sm[t] += add; __syncthreads();
    }
    int off = g_boff[blockIdx.x] + sm[t] - c;
    if (i < NN) g_off[i] = off;
    if (i == NN - 1) g_off[NN] = off + c;
}
__global__ __launch_bounds__(256) void fill_kernel(const void* __restrict__ edge) {
    int e = blockIdx.x * blockDim.x + threadIdx.x;
    if (e >= EE) return;
    int r = ld_eidx(edge, e);
    int c = ld_eidx(edge, EE + e);
    int pos = atomicAdd(&g_cur[c], 1);
    int slot = g_off[c] + pos;
    g_src[slot] = r;
    g_nrm[slot] = g_deg[r] * g_deg[c];   // dinv ready (blocksum ran earlier)
}

// ---------------- weight prep: W^T split to bf16 hi/lo ----------------
__global__ __launch_bounds__(256) void wtprep_kernel(const float* __restrict__ W_in,
                                                     const float* __restrict__ W_conv) {
    int idx = blockIdx.x * blockDim.x + threadIdx.x;   // 4*16384
    if (idx >= 4 * HH * HH) return;
    int w = idx >> 14, r = idx & 16383;
    int n = r >> 7, k = r & 127;
    const float* W = (w == 0) ? W_in : (W_conv + (size_t)(w - 1) * HH * HH);
    unsigned short hi, lo;
    split_bf(W[(size_t)k * HH + n], hi, lo);
    ((unsigned short*)g_wthi)[idx] = hi;
    ((unsigned short*)g_wtlo)[idx] = lo;
}

// ---------------- tensor-core GEMM via mma.sync bf16 split ----------------
// C[n][j] = sum_k A[n][k] * W[k][j]  with A = x (MODE 0) or g_h (MODE 1/2).
// MODE 0: g_h = C + bias
// MODE 1: g_m = C
// MODE 2: A = g_h + relu(g_hn*scale+shift) (written back to g_h), g_m = C
#define KS 136                                 // padded row stride (bf16 elems)
#define SM_AHI 0
#define SM_ALO (128 * KS * 2)
#define SM_BHI (2 * 128 * KS * 2)
#define SM_BLO (3 * 128 * KS * 2)
#define SM_TOT (4 * 128 * KS * 2)              // 139264 bytes

template <int MODE>
__global__ __launch_bounds__(256, 1) void gemm_kernel(
    const float* __restrict__ Ain, int widx, const float* __restrict__ bias)
{
    extern __shared__ char smem[];
    const unsigned short* Whi = (const unsigned short*)g_wthi + (size_t)widx * HH * HH;
    const unsigned short* Wlo = (const unsigned short*)g_wtlo + (size_t)widx * HH * HH;

    int tid  = threadIdx.x;
    int n0   = blockIdx.x * 128;
    int lane = tid & 31;
    int wid  = tid >> 5;
    int gid  = lane >> 2;          // 0..7
    int tg   = lane & 3;           // 0..3
    int m_base = (wid >> 1) * 32;  // warp row base within tile
    int n_base = (wid & 1) * 64;   // warp col base within tile

    // ---- stage A (split fp32 -> bf16 hi/lo), optionally fused BN-apply ----
    for (int t = 0; t < 16; t++) {
        int idx = tid + t * 256;               // 4096 float4 slots
        int r   = idx >> 5;                    // tile row
        int c4  = idx & 31;                    // float4 index in row
        int col = c4 * 4;
        int n   = n0 + r;
        float4 v = make_float4(0.f, 0.f, 0.f, 0.f);
        if (n < NN) {
            if (MODE == 0) {
                v = *(const float4*)(Ain + (size_t)n * 128 + col);
            } else if (MODE == 1) {
                v = *(const float4*)(g_h + (size_t)n * 128 + col);
            } else {
                float4 h  = *(const float4*)(g_h  + (size_t)n * 128 + col);
                float4 hn = *(const float4*)(g_hn + (size_t)n * 128 + col);
                float4 sc = *(const float4*)(g_scale + col);
                float4 sh = *(const float4*)(g_shift + col);
                v.x = h.x + fmaxf(hn.x * sc.x + sh.x, 0.f);
                v.y = h.y + fmaxf(hn.y * sc.y + sh.y, 0.f);
                v.z = h.z + fmaxf(hn.z * sc.z + sh.z, 0.f);
                v.w = h.w + fmaxf(hn.w * sc.w + sh.w, 0.f);
                *(float4*)(g_h + (size_t)n * 128 + col) = v;   // row owned by this block
            }
        }
        unsigned short h0, h1, h2, h3, l0, l1, l2, l3;
        split_bf(v.x, h0, l0); split_bf(v.y, h1, l1);
        split_bf(v.z, h2, l2); split_bf(v.w, h3, l3);
        uint32_t off = (uint32_t)r * (KS * 2) + col * 2;
        *(uint32_t*)(smem + SM_AHI + off)     = pack_us(h0, h1);
        *(uint32_t*)(smem + SM_AHI + off + 4) = pack_us(h2, h3);
        *(uint32_t*)(smem + SM_ALO + off)     = pack_us(l0, l1);
        *(uint32_t*)(smem + SM_ALO + off + 4) = pack_us(l2, l3);
    }
    // ---- stage B = W^T hi/lo (bf16, [n][k]) ----
    for (int t = 0; t < 8; t++) {
        int idx = tid + t * 256;               // 2048 uint4 slots
        int r = idx >> 4, q = idx & 15;        // row n, 8-bf16 chunk
        uint32_t off = (uint32_t)r * (KS * 2) + q * 16;
        *(uint4*)(smem + SM_BHI + off) = *(const uint4*)(Whi + (size_t)r * 128 + q * 8);
        *(uint4*)(smem + SM_BLO + off) = *(const uint4*)(Wlo + (size_t)r * 128 + q * 8);
    }
    __syncthreads();

    // ---- compute: 2 m-frags x 8 n-frags of m16n8, K = 8 steps of 16 ----
    float acc[2][8][4];
#pragma unroll
    for (int f = 0; f < 2; f++)
#pragma unroll
        for (int j = 0; j < 8; j++)
#pragma unroll
            for (int c = 0; c < 4; c++) acc[f][j][c] = 0.f;

#pragma unroll
    for (int ks = 0; ks < 8; ks++) {
        int k0 = ks * 16;
        uint32_t ahi[2][4], alo[2][4];
#pragma unroll
        for (int f = 0; f < 2; f++) {
            uint32_t r0 = (uint32_t)(m_base + f * 16 + gid) * (KS * 2);
            uint32_t r1 = r0 + 8 * (KS * 2);
            uint32_t cA = (uint32_t)(k0 + 2 * tg) * 2;
            ahi[f][0] = *(const uint32_t*)(smem + SM_AHI + r0 + cA);
            ahi[f][1] = *(const uint32_t*)(smem + SM_AHI + r1 + cA);
            ahi[f][2] = *(const uint32_t*)(smem + SM_AHI + r0 + cA + 16);
            ahi[f][3] = *(const uint32_t*)(smem + SM_AHI + r1 + cA + 16);
            alo[f][0] = *(const uint32_t*)(smem + SM_ALO + r0 + cA);
            alo[f][1] = *(const uint32_t*)(smem + SM_ALO + r1 + cA);
            alo[f][2] = *(const uint32_t*)(smem + SM_ALO + r0 + cA + 16);
            alo[f][3] = *(const uint32_t*)(smem + SM_ALO + r1 + cA + 16);
        }
#pragma unroll
        for (int j = 0; j < 8; j++) {
            uint32_t rn = (uint32_t)(n_base + j * 8 + gid) * (KS * 2);
            uint32_t cB = (uint32_t)(k0 + 2 * tg) * 2;
            uint32_t bh0 = *(const uint32_t*)(smem + SM_BHI + rn + cB);
            uint32_t bh1 = *(const uint32_t*)(smem + SM_BHI + rn + cB + 16);
            uint32_t bl0 = *(const uint32_t*)(smem + SM_BLO + rn + cB);
            uint32_t bl1 = *(const uint32_t*)(smem + SM_BLO + rn + cB + 16);
#pragma unroll
            for (int f = 0; f < 2; f++) {
                mma_bf16(acc[f][j], ahi[f], bh0, bh1);
                mma_bf16(acc[f][j], ahi[f], bl0, bl1);
                mma_bf16(acc[f][j], alo[f], bh0, bh1);
            }
        }
    }

    // ---- epilogue: direct float2 stores ----
#pragma unroll
    for (int f = 0; f < 2; f++) {
        int r0 = n0 + m_base + f * 16 + gid;
        int r1 = r0 + 8;
#pragma unroll
        for (int j = 0; j < 8; j++) {
            int col = n_base + j * 8 + 2 * tg;
            if (MODE == 0) {
                float bx = bias[col], by = bias[col + 1];
                if (r0 < NN) *(float2*)(g_h + (size_t)r0 * 128 + col) =
                    make_float2(acc[f][j][0] + bx, acc[f][j][1] + by);
                if (r1 < NN) *(float2*)(g_h + (size_t)r1 * 128 + col) =
                    make_float2(acc[f][j][2] + bx, acc[f][j][3] + by);
            } else {
                if (r0 < NN) *(float2*)(g_m + (size_t)r0 * 128 + col) =
                    make_float2(acc[f][j][0], acc[f][j][1]);
                if (r1 < NN) *(float2*)(g_m + (size_t)r1 * 128 + col) =
                    make_float2(acc[f][j][2], acc[f][j][3]);
            }
        }
    }
}

// ---------------- aggregation (CSR gather) + fused BN statistics ----------------
// hn[n] = bias + m[n]*dinv[n]^2 + sum_e m[src_e]*nrm_e ; nrm precomputed.
__global__ __launch_bounds__(256) void agg_kernel(const float* __restrict__ bias) {
    int lane = threadIdx.x & 31;
    int w    = threadIdx.x >> 5;
    float4 b4 = ((const float4*)bias)[lane];

    float s0 = 0.f, s1 = 0.f, s2 = 0.f, s3 = 0.f;
    float q0 = 0.f, q1 = 0.f, q2 = 0.f, q3 = 0.f;

    for (int n = blockIdx.x * 8 + w; n < NN; n += gridDim.x * 8) {
        float dc = g_deg[n];
        float d2 = dc * dc;
        float4 m = ((const float4*)(g_m + (size_t)n * 128))[lane];
        float4 acc;
        acc.x = b4.x + m.x * d2;
        acc.y = b4.y + m.y * d2;
        acc.z = b4.z + m.z * d2;
        acc.w = b4.w + m.w * d2;

        int beg = g_off[n], end = g_off[n + 1];
        int i = beg;
        for (; i + 2 <= end; i += 2) {          // unrolled: 2 independent gathers
            int   r0  = g_src[i];
            int   r1  = g_src[i + 1];
            float nr0 = g_nrm[i];
            float nr1 = g_nrm[i + 1];
            float4 v0 = ((const float4*)(g_m + (size_t)r0 * 128))[lane];
            float4 v1 = ((const float4*)(g_m + (size_t)r1 * 128))[lane];
            acc.x += v0.x * nr0 + v1.x * nr1;
            acc.y += v0.y * nr0 + v1.y * nr1;
            acc.z += v0.z * nr0 + v1.z * nr1;
            acc.w += v0.w * nr0 + v1.w * nr1;
        }
        if (i < end) {
            int   r0  = g_src[i];
            float nr0 = g_nrm[i];
            float4 v0 = ((const float4*)(g_m + (size_t)r0 * 128))[lane];
            acc.x += v0.x * nr0; acc.y += v0.y * nr0;
            acc.z += v0.z * nr0; acc.w += v0.w * nr0;
        }
        ((float4*)(g_hn + (size_t)n * 128))[lane] = acc;

        s0 += acc.x; q0 += acc.x * acc.x;
        s1 += acc.y; q1 += acc.y * acc.y;
        s2 += acc.z; q2 += acc.z * acc.z;
        s3 += acc.w; q3 += acc.w * acc.w;
    }

    __shared__ float sb[2][8][128];
    int ch = lane * 4;
    sb[0][w][ch + 0] = s0; sb[0][w][ch + 1] = s1;
    sb[0][w][ch + 2] = s2; sb[0][w][ch + 3] = s3;
    sb[1][w][ch + 0] = q0; sb[1][w][ch + 1] = q1;
    sb[1][w][ch + 2] = q2; sb[1][w][ch + 3] = q3;
    __syncthreads();

    int t = threadIdx.x;
    if (t < 128) {
        float a = 0.f;
#pragma unroll
        for (int ww = 0; ww < 8; ww++) a += sb[0][ww][t];
        atomicAdd(&g_sum[t], (double)a);
    } else {
        int tc = t - 128;
        float a = 0.f;
#pragma unroll
        for (int ww = 0; ww < 8; ww++) a += sb[1][ww][tc];
        atomicAdd(&g_sumsq[tc], (double)a);
    }
}

// ---------------- batchnorm finalize (self-resetting stats) ----------------
__global__ void bn_finalize_kernel(const float* __restrict__ gamma,
                                   const float* __restrict__ beta) {
    int j = threadIdx.x;
    if (j >= HH) return;
    float mu  = (float)(g_sum[j] / (double)NN);
    float var = (float)(g_sumsq[j] / (double)NN) - mu * mu;
    float inv = rsqrtf(var + 1e-5f);
    float sc  = inv * gamma[j];
    g_scale[j] = sc;
    g_shift[j] = beta[j] - mu * sc;
    g_sum[j] = 0.0; g_sumsq[j] = 0.0;   // ready for next layer
}

// ---------------- pool with fused final BN apply (batch is sorted) ----------------
#define POOL_C 32
__global__ __launch_bounds__(256) void pool_kernel(const void* __restrict__ batch) {
    int lane = threadIdx.x & 31;
    int w    = threadIdx.x >> 5;
    int n0   = (blockIdx.x * 8 + w) * POOL_C;
    if (n0 >= NN) return;
    int nend = n0 + POOL_C;
    if (nend > NN) nend = NN;

    float4 sc = ((const float4*)g_scale)[lane];
    float4 sh = ((const float4*)g_shift)[lane];

    float4 acc = make_float4(0.f, 0.f, 0.f, 0.f);
    int curg = -1, cnt = 0;

    for (int n = n0; n < nend; n++) {
        int g = ld_bidx(batch, n);
        if (g != curg) {
            if (curg >= 0) {
                float* dst = g_gsum + (size_t)curg * 128 + lane * 4;
                atomicAdd(dst + 0, acc.x); atomicAdd(dst + 1, acc.y);
                atomicAdd(dst + 2, acc.z); atomicAdd(dst + 3, acc.w);
                if (lane == 0) atomicAdd(&g_gcnt[curg], (float)cnt);
            }
            curg = g;
            acc = make_float4(0.f, 0.f, 0.f, 0.f);
            cnt = 0;
        }
        float4 h  = ((const float4*)(g_h  + (size_t)n * 128))[lane];
        float4 hn = ((const float4*)(g_hn + (size_t)n * 128))[lane];
        acc.x += h.x + fmaxf(hn.x * sc.x + sh.x, 0.f);
        acc.y += h.y + fmaxf(hn.y * sc.y + sh.y, 0.f);
        acc.z += h.z + fmaxf(hn.z * sc.z + sh.z, 0.f);
        acc.w += h.w + fmaxf(hn.w * sc.w + sh.w, 0.f);
        cnt++;
    }
    if (curg >= 0) {
        float* dst = g_gsum + (size_t)curg * 128 + lane * 4;
        atomicAdd(dst + 0, acc.x); atomicAdd(dst + 1, acc.y);
        atomicAdd(dst + 2, acc.z); atomicAdd(dst + 3, acc.w);
        if (lane == 0) atomicAdd(&g_gcnt[curg], (float)cnt);
    }
}

// ---------------- output head: out = (gsum/cnt) @ W_out + b_out ----------------
__global__ __launch_bounds__(128) void out_kernel(const float* __restrict__ Wout,
                                                  const float* __restrict__ bout,
                                                  float* __restrict__ out) {
    __shared__ float row[128];
    int g = blockIdx.x, j = threadIdx.x;
    float cnt = fmaxf(g_gcnt[g], 1.0f);
    row[j] = g_gsum[(size_t)g * 128 + j] / cnt;
    __syncthreads();
    float acc = bout[j];
#pragma unroll 8
    for (int k = 0; k < 128; k++)
        acc = fmaf(row[k], Wout[(size_t)k * 128 + j], acc);
    out[(size_t)g * 128 + j] = acc;
}

// ---------------- launch ----------------
extern "C" void kernel_launch(void* const* d_in, const int* in_sizes, int n_in,
                              void* d_out, int out_size) {
    const float* x      = (const float*)d_in[0];
    const float* W_in   = (const float*)d_in[1];
    const float* b_in   = (const float*)d_in[2];
    const float* W_conv = (const float*)d_in[3];
    const float* b_conv = (const float*)d_in[4];
    const float* gamma  = (const float*)d_in[5];
    const float* beta   = (const float*)d_in[6];
    const float* W_out  = (const float*)d_in[7];
    const float* b_out  = (const float*)d_in[8];
    const void*  edge   = d_in[9];
    const void*  batch  = d_in[10];
    float* out = (float*)d_out;

    // idempotent; safe under graph capture
    cudaFuncSetAttribute(gemm_kernel<0>, cudaFuncAttributeMaxDynamicSharedMemorySize, SM_TOT);
    cudaFuncSetAttribute(gemm_kernel<1>, cudaFuncAttributeMaxDynamicSharedMemorySize, SM_TOT);
    cudaFuncSetAttribute(gemm_kernel<2>, cudaFuncAttributeMaxDynamicSharedMemorySize, SM_TOT);

    const int GEMM_GRID = (NN + 127) / 128;            // 1563
    const int SCAN_GRID = (NN + 255) / 256;            // 782
    const int AGG_GRID  = 3125;                        // 8 nodes/warp
    const int POOL_GRID = (NN + 8 * POOL_C - 1) / (8 * POOL_C);

    detect_kernel<<<1, 1>>>(edge, batch);
    setup_kernel<<<(GG * HH + 255) / 256, 256>>>();
    deg_kernel<<<(EE + 255) / 256, 256>>>(edge);

    blocksum_kernel<<<SCAN_GRID, 256>>>();             // + dinv fused
    scanb_kernel<<<1, 1024>>>(SCAN_GRID);
    offsets_kernel<<<SCAN_GRID, 256>>>();
    fill_kernel<<<(EE + 255) / 256, 256>>>(edge);      // + nrm precompute

    wtprep_kernel<<<(4 * HH * HH + 255) / 256, 256>>>(W_in, W_conv);

    gemm_kernel<0><<<GEMM_GRID, 256, SM_TOT>>>(x, 0, b_in);

    for (int l = 0; l < LL; l++) {
        if (l == 0)
            gemm_kernel<1><<<GEMM_GRID, 256, SM_TOT>>>(nullptr, 1 + l, nullptr);
        else
            gemm_kernel<2><<<GEMM_GRID, 256, SM_TOT>>>(nullptr, 1 + l, nullptr);
        agg_kernel<<<AGG_GRID, 256>>>(b_conv + (size_t)l * HH);
        bn_finalize_kernel<<<1, 128>>>(gamma + (size_t)l * HH, beta + (size_t)l * HH);
    }

    pool_kernel<<<POOL_GRID, 256>>>(batch);   // applies layer-3 BN inline
    out_kernel<<<GG, 128>>>(W_out, b_out, out);
}

// round 12
// speedup vs baseline: 1.2964x; 1.2964x over previous
#include <cuda_runtime.h>
#include <cuda_bf16.h>
#include <cstdint>

#define NN 200000
#define EE 400000
#define HH 128
#define GG 4096
#define LL 3

// ---------------- scratch (static __device__, allocation-free) ----------------
__device__ __align__(16) float g_h [(size_t)NN * HH];   // node features (residual)
__device__ __align__(16) float g_m [(size_t)NN * HH];   // per-layer linear output
__device__ __align__(16) float g_hn[(size_t)NN * HH];   // aggregated messages
__device__ __align__(16) __nv_bfloat16 g_wthi[4 * HH * HH];  // W^T hi, [w][n][k]
__device__ __align__(16) __nv_bfloat16 g_wtlo[4 * HH * HH];  // W^T lo
__device__ float  g_deg[NN];
__device__ int    g_icnt[NN];
__device__ int    g_off[NN + 1];
__device__ int    g_cur[NN];
__device__ int    g_src[EE];
__device__ float  g_nrm[EE];                            // dinv[src]*dinv[dst] per CSR slot
__device__ int    g_bsum[1024];
__device__ int    g_boff[1024];
__device__ double g_sum[HH];
__device__ double g_sumsq[HH];
__device__ __align__(16) float g_scale[HH];
__device__ __align__(16) float g_shift[HH];
__device__ __align__(16) float g_gsum[(size_t)GG * HH];
__device__ float g_gcnt[GG];
__device__ int   g_idx64;
__device__ int   g_bidx64;

// ---------------- helpers ----------------
__device__ __forceinline__ void split_bf(float v, unsigned short& hi, unsigned short& lo) {
    __nv_bfloat16 h = __float2bfloat16(v);
    __nv_bfloat16 l = __float2bfloat16(v - __bfloat162float(h));
    hi = *(unsigned short*)&h;
    lo = *(unsigned short*)&l;
}
__device__ __forceinline__ uint32_t pack_us(unsigned short a, unsigned short b) {
    return (uint32_t)a | ((uint32_t)b << 16);
}
__device__ __forceinline__ void mma_bf16(float* d, const uint32_t* a, uint32_t b0, uint32_t b1) {
    asm volatile(
        "mma.sync.aligned.m16n8k16.row.col.f32.bf16.bf16.f32 "
        "{%0,%1,%2,%3}, {%4,%5,%6,%7}, {%8,%9}, {%0,%1,%2,%3};"
        : "+f"(d[0]), "+f"(d[1]), "+f"(d[2]), "+f"(d[3])
        : "r"(a[0]), "r"(a[1]), "r"(a[2]), "r"(a[3]), "r"(b0), "r"(b1));
}

// ---------------- index width detection (bounds-safe for both widths) ----------------
__global__ void detect_kernel(const void* edge, const void* batch) {
    const int* we = (const int*)edge;
    const int* wb = (const int*)batch;
    int nz_e = 0, nz_b = 0;
    for (int i = 0; i < 64; i++) {
        nz_e |= we[1 + 2 * (i * (EE / 64))];
        nz_b |= wb[(NN - 1) - 2 * i];
    }
    g_idx64  = (nz_e == 0) ? 1 : 0;
    g_bidx64 = (nz_b == 0) ? 1 : 0;
}
__device__ __forceinline__ int ld_eidx(const void* p, int i) {
    return g_idx64 ? (int)((const long long*)p)[i] : ((const int*)p)[i];
}
__device__ __forceinline__ int ld_bidx(const void* p, int i) {
    return g_bidx64 ? (int)((const long long*)p)[i] : ((const int*)p)[i];
}

// ---------------- setup / degree / CSR ----------------
__global__ void setup_kernel() {
    int i = blockIdx.x * blockDim.x + threadIdx.x;
    if (i < NN) { g_icnt[i] = 0; g_cur[i] = 0; }
    if (i < GG * HH) g_gsum[i] = 0.0f;
    if (i < GG) g_gcnt[i] = 0.0f;
    if (i < HH) { g_sum[i] = 0.0; g_sumsq[i] = 0.0; }
}
__global__ void deg_kernel(const void* edge) {
    int e = blockIdx.x * blockDim.x + threadIdx.x;
    if (e < EE) atomicAdd(&g_icnt[ld_eidx(edge, EE + e)], 1);
}
// blocksum + dinv fused
__global__ __launch_bounds__(256) void blocksum_kernel() {
    __shared__ int sm[256];
    int t = threadIdx.x, i = blockIdx.x * 256 + t;
    int c = (i < NN) ? g_icnt[i] : 0;
    if (i < NN) g_deg[i] = rsqrtf((float)(c + 1));
    sm[t] = c;
    __syncthreads();
    for (int d = 128; d > 0; d >>= 1) { if (t < d) sm[t] += sm[t + d]; __syncthreads(); }
    if (t == 0) g_bsum[blockIdx.x] = sm[0];
}
__global__ __launch_bounds__(1024) void scanb_kernel(int nblocks) {
    __shared__ int sm[1024];
    int t = threadIdx.x;
    int v = (t < nblocks) ? g_bsum[t] : 0;
    sm[t] = v;
    __syncthreads();
    for (int d = 1; d < 1024; d <<= 1) {
        int add = (t >= d) ? sm[t - d] : 0;
        __syncthreads(); sm[t] += add; __syncthreads();
    }
    g_boff[t] = sm[t] - v;
}
__global__ __launch_bounds__(256) void offsets_kernel() {
    __shared__ int sm[256];
    int t = threadIdx.x, i = blockIdx.x * 256 + t;
    int c = (i < NN) ? g_icnt[i] : 0;
    sm[t] = c;
    __syncthreads();
    for (int d = 1; d < 256; d <<= 1) {
        int add = (t >= d) ? sm[t - d] : 0;
        __syncthreads(); sm[t] += add; __syncthreads();
    }
    int off = g_boff[blockIdx.x] + sm[t] - c;
    if (i < NN) g_off[i] = off;
    if (i == NN - 1) g_off[NN] = off + c;
}
__global__ __launch_bounds__(256) void fill_kernel(const void* __restrict__ edge) {
    int e = blockIdx.x * blockDim.x + threadIdx.x;
    if (e >= EE) return;
    int r = ld_eidx(edge, e);
    int c = ld_eidx(edge, EE + e);
    int pos = atomicAdd(&g_cur[c], 1);
    int slot = g_off[c] + pos;
    g_src[slot] = r;
    g_nrm[slot] = g_deg[r] * g_deg[c];   // dinv ready (blocksum ran earlier)
}

// ---------------- weight prep: W^T split to bf16 hi/lo ----------------
__global__ __launch_bounds__(256) void wtprep_kernel(const float* __restrict__ W_in,
                                                     const float* __restrict__ W_conv) {
    int idx = blockIdx.x * blockDim.x + threadIdx.x;   // 4*16384
    if (idx >= 4 * HH * HH) return;
    int w = idx >> 14, r = idx & 16383;
    int n = r >> 7, k = r & 127;
    const float* W = (w == 0) ? W_in : (W_conv + (size_t)(w - 1) * HH * HH);
    unsigned short hi, lo;
    split_bf(W[(size_t)k * HH + n], hi, lo);
    ((unsigned short*)g_wthi)[idx] = hi;
    ((unsigned short*)g_wtlo)[idx] = lo;
}

// ---------------- tensor-core GEMM via mma.sync bf16 split ----------------
// C[n][j] = sum_k A[n][k] * W[k][j]  with A = x (MODE 0) or g_h (MODE 1/2).
// MODE 0: g_h = C + bias
// MODE 1: g_m = C
// MODE 2: A = g_h + relu(g_hn*scale+shift) (written back to g_h), g_m = C
#define KS 136                                 // padded row stride (bf16 elems)
#define SM_AHI 0
#define SM_ALO (128 * KS * 2)
#define SM_BHI (2 * 128 * KS * 2)
#define SM_BLO (3 * 128 * KS * 2)
#define SM_TOT (4 * 128 * KS * 2)              // 139264 bytes

template <int MODE>
__global__ __launch_bounds__(256, 1) void gemm_kernel(
    const float* __restrict__ Ain, int widx, const float* __restrict__ bias)
{
    extern __shared__ char smem[];
    const unsigned short* Whi = (const unsigned short*)g_wthi + (size_t)widx * HH * HH;
    const unsigned short* Wlo = (const unsigned short*)g_wtlo + (size_t)widx * HH * HH;

    int tid  = threadIdx.x;
    int n0   = blockIdx.x * 128;
    int lane = tid & 31;
    int wid  = tid >> 5;
    int gid  = lane >> 2;          // 0..7
    int tg   = lane & 3;           // 0..3
    int m_base = (wid >> 1) * 32;  // warp row base within tile
    int n_base = (wid & 1) * 64;   // warp col base within tile

    // ---- stage A (split fp32 -> bf16 hi/lo), optionally fused BN-apply ----
    for (int t = 0; t < 16; t++) {
        int idx = tid + t * 256;               // 4096 float4 slots
        int r   = idx >> 5;                    // tile row
        int c4  = idx & 31;                    // float4 index in row
        int col = c4 * 4;
        int n   = n0 + r;
        float4 v = make_float4(0.f, 0.f, 0.f, 0.f);
        if (n < NN) {
            if (MODE == 0) {
                v = *(const float4*)(Ain + (size_t)n * 128 + col);
            } else if (MODE == 1) {
                v = *(const float4*)(g_h + (size_t)n * 128 + col);
            } else {
                float4 h  = *(const float4*)(g_h  + (size_t)n * 128 + col);
                float4 hn = *(const float4*)(g_hn + (size_t)n * 128 + col);
                float4 sc = *(const float4*)(g_scale + col);
                float4 sh = *(const float4*)(g_shift + col);
                v.x = h.x + fmaxf(hn.x * sc.x + sh.x, 0.f);
                v.y = h.y + fmaxf(hn.y * sc.y + sh.y, 0.f);
                v.z = h.z + fmaxf(hn.z * sc.z + sh.z, 0.f);
                v.w = h.w + fmaxf(hn.w * sc.w + sh.w, 0.f);
                *(float4*)(g_h + (size_t)n * 128 + col) = v;   // row owned by this block
            }
        }
        unsigned short h0, h1, h2, h3, l0, l1, l2, l3;
        split_bf(v.x, h0, l0); split_bf(v.y, h1, l1);
        split_bf(v.z, h2, l2); split_bf(v.w, h3, l3);
        uint32_t off = (uint32_t)r * (KS * 2) + col * 2;
        *(uint32_t*)(smem + SM_AHI + off)     = pack_us(h0, h1);
        *(uint32_t*)(smem + SM_AHI + off + 4) = pack_us(h2, h3);
        *(uint32_t*)(smem + SM_ALO + off)     = pack_us(l0, l1);
        *(uint32_t*)(smem + SM_ALO + off + 4) = pack_us(l2, l3);
    }
    // ---- stage B = W^T hi/lo (bf16, [n][k]) ----
    for (int t = 0; t < 8; t++) {
        int idx = tid + t * 256;               // 2048 uint4 slots
        int r = idx >> 4, q = idx & 15;        // row n, 8-bf16 chunk
        uint32_t off = (uint32_t)r * (KS * 2) + q * 16;
        *(uint4*)(smem + SM_BHI + off) = *(const uint4*)(Whi + (size_t)r * 128 + q * 8);
        *(uint4*)(smem + SM_BLO + off) = *(const uint4*)(Wlo + (size_t)r * 128 + q * 8);
    }
    __syncthreads();

    // ---- compute: 2 m-frags x 8 n-frags of m16n8, K = 8 steps of 16 ----
    float acc[2][8][4];
#pragma unroll
    for (int f = 0; f < 2; f++)
#pragma unroll
        for (int j = 0; j < 8; j++)
#pragma unroll
            for (int c = 0; c < 4; c++) acc[f][j][c] = 0.f;

#pragma unroll
    for (int ks = 0; ks < 8; ks++) {
        int k0 = ks * 16;
        uint32_t ahi[2][4], alo[2][4];
#pragma unroll
        for (int f = 0; f < 2; f++) {
            uint32_t r0 = (uint32_t)(m_base + f * 16 + gid) * (KS * 2);
            uint32_t r1 = r0 + 8 * (KS * 2);
            uint32_t cA = (uint32_t)(k0 + 2 * tg) * 2;
            ahi[f][0] = *(const uint32_t*)(smem + SM_AHI + r0 + cA);
            ahi[f][1] = *(const uint32_t*)(smem + SM_AHI + r1 + cA);
            ahi[f][2] = *(const uint32_t*)(smem + SM_AHI + r0 + cA + 16);
            ahi[f][3] = *(const uint32_t*)(smem + SM_AHI + r1 + cA + 16);
            alo[f][0] = *(const uint32_t*)(smem + SM_ALO + r0 + cA);
            alo[f][1] = *(const uint32_t*)(smem + SM_ALO + r1 + cA);
            alo[f][2] = *(const uint32_t*)(smem + SM_ALO + r0 + cA + 16);
            alo[f][3] = *(const uint32_t*)(smem + SM_ALO + r1 + cA + 16);
        }
#pragma unroll
        for (int j = 0; j < 8; j++) {
            uint32_t rn = (uint32_t)(n_base + j * 8 + gid) * (KS * 2);
            uint32_t cB = (uint32_t)(k0 + 2 * tg) * 2;
            uint32_t bh0 = *(const uint32_t*)(smem + SM_BHI + rn + cB);
            uint32_t bh1 = *(const uint32_t*)(smem + SM_BHI + rn + cB + 16);
            uint32_t bl0 = *(const uint32_t*)(smem + SM_BLO + rn + cB);
            uint32_t bl1 = *(const uint32_t*)(smem + SM_BLO + rn + cB + 16);
#pragma unroll
            for (int f = 0; f < 2; f++) {
                mma_bf16(acc[f][j], ahi[f], bh0, bh1);
                mma_bf16(acc[f][j], ahi[f], bl0, bl1);
                mma_bf16(acc[f][j], alo[f], bh0, bh1);
            }
        }
    }

    // ---- epilogue: direct float2 stores ----
#pragma unroll
    for (int f = 0; f < 2; f++) {
        int r0 = n0 + m_base + f * 16 + gid;
        int r1 = r0 + 8;
#pragma unroll
        for (int j = 0; j < 8; j++) {
            int col = n_base + j * 8 + 2 * tg;
            if (MODE == 0) {
                float bx = bias[col], by = bias[col + 1];
                if (r0 < NN) *(float2*)(g_h + (size_t)r0 * 128 + col) =
                    make_float2(acc[f][j][0] + bx, acc[f][j][1] + by);
                if (r1 < NN) *(float2*)(g_h + (size_t)r1 * 128 + col) =
                    make_float2(acc[f][j][2] + bx, acc[f][j][3] + by);
            } else {
                if (r0 < NN) *(float2*)(g_m + (size_t)r0 * 128 + col) =
                    make_float2(acc[f][j][0], acc[f][j][1]);
                if (r1 < NN) *(float2*)(g_m + (size_t)r1 * 128 + col) =
                    make_float2(acc[f][j][2], acc[f][j][3]);
            }
        }
    }
}

// ---------------- aggregation (CSR gather) + fused BN statistics ----------------
// hn[n] = bias + m[n]*dinv[n]^2 + sum_e m[src_e]*nrm_e ; nrm precomputed.
__global__ __launch_bounds__(256) void agg_kernel(const float* __restrict__ bias) {
    int lane = threadIdx.x & 31;
    int w    = threadIdx.x >> 5;
    float4 b4 = ((const float4*)bias)[lane];

    float s0 = 0.f, s1 = 0.f, s2 = 0.f, s3 = 0.f;
    float q0 = 0.f, q1 = 0.f, q2 = 0.f, q3 = 0.f;

    for (int n = blockIdx.x * 8 + w; n < NN; n += gridDim.x * 8) {
        float dc = g_deg[n];
        float d2 = dc * dc;
        float4 m = ((const float4*)(g_m + (size_t)n * 128))[lane];
        float4 acc;
        acc.x = b4.x + m.x * d2;
        acc.y = b4.y + m.y * d2;
        acc.z = b4.z + m.z * d2;
        acc.w = b4.w + m.w * d2;

        int beg = g_off[n], end = g_off[n + 1];
        for (int i = beg; i < end; i++) {
            int   r  = g_src[i];
            float nr = g_nrm[i];
            float4 v = ((const float4*)(g_m + (size_t)r * 128))[lane];
            acc.x += v.x * nr; acc.y += v.y * nr;
            acc.z += v.z * nr; acc.w += v.w * nr;
        }
        ((float4*)(g_hn + (size_t)n * 128))[lane] = acc;

        s0 += acc.x; q0 += acc.x * acc.x;
        s1 += acc.y; q1 += acc.y * acc.y;
        s2 += acc.z; q2 += acc.z * acc.z;
        s3 += acc.w; q3 += acc.w * acc.w;
    }

    __shared__ float sb[2][8][128];
    int ch = lane * 4;
    sb[0][w][ch + 0] = s0; sb[0][w][ch + 1] = s1;
    sb[0][w][ch + 2] = s2; sb[0][w][ch + 3] = s3;
    sb[1][w][ch + 0] = q0; sb[1][w][ch + 1] = q1;
    sb[1][w][ch + 2] = q2; sb[1][w][ch + 3] = q3;
    __syncthreads();

    int t = threadIdx.x;
    if (t < 128) {
        float a = 0.f;
#pragma unroll
        for (int ww = 0; ww < 8; ww++) a += sb[0][ww][t];
        atomicAdd(&g_sum[t], (double)a);
    } else {
        int tc = t - 128;
        float a = 0.f;
#pragma unroll
        for (int ww = 0; ww < 8; ww++) a += sb[1][ww][tc];
        atomicAdd(&g_sumsq[tc], (double)a);
    }
}

// ---------------- batchnorm finalize (self-resetting stats) ----------------
__global__ void bn_finalize_kernel(const float* __restrict__ gamma,
                                   const float* __restrict__ beta) {
    int j = threadIdx.x;
    if (j >= HH) return;
    float mu  = (float)(g_sum[j] / (double)NN);
    float var = (float)(g_sumsq[j] / (double)NN) - mu * mu;
    float inv = rsqrtf(var + 1e-5f);
    float sc  = inv * gamma[j];
    g_scale[j] = sc;
    g_shift[j] = beta[j] - mu * sc;
    g_sum[j] = 0.0; g_sumsq[j] = 0.0;   // ready for next layer
}

// ---------------- pool with fused final BN apply (batch is sorted) ----------------
#define POOL_C 64
__global__ __launch_bounds__(256) void pool_kernel(const void* __restrict__ batch) {
    int lane = threadIdx.x & 31;
    int w    = threadIdx.x >> 5;
    int n0   = (blockIdx.x * 8 + w) * POOL_C;
    if (n0 >= NN) return;
    int nend = n0 + POOL_C;
    if (nend > NN) nend = NN;

    float4 sc = ((const float4*)g_scale)[lane];
    float4 sh = ((const float4*)g_shift)[lane];

    float4 acc = make_float4(0.f, 0.f, 0.f, 0.f);
    int curg = -1, cnt = 0;

    for (int n = n0; n < nend; n++) {
        int g = ld_bidx(batch, n);
        if (g != curg) {
            if (curg >= 0) {
                float* dst = g_gsum + (size_t)curg * 128 + lane * 4;
                atomicAdd(dst + 0, acc.x); atomicAdd(dst + 1, acc.y);
                atomicAdd(dst + 2, acc.z); atomicAdd(dst + 3, acc.w);
                if (lane == 0) atomicAdd(&g_gcnt[curg], (float)cnt);
            }
            curg = g;
            acc = make_float4(0.f, 0.f, 0.f, 0.f);
            cnt = 0;
        }
        float4 h  = ((const float4*)(g_h  + (size_t)n * 128))[lane];
        float4 hn = ((const float4*)(g_hn + (size_t)n * 128))[lane];
        acc.x += h.x + fmaxf(hn.x * sc.x + sh.x, 0.f);
        acc.y += h.y + fmaxf(hn.y * sc.y + sh.y, 0.f);
        acc.z += h.z + fmaxf(hn.z * sc.z + sh.z, 0.f);
        acc.w += h.w + fmaxf(hn.w * sc.w + sh.w, 0.f);
        cnt++;
    }
    if (curg >= 0) {
        float* dst = g_gsum + (size_t)curg * 128 + lane * 4;
        atomicAdd(dst + 0, acc.x); atomicAdd(dst + 1, acc.y);
        atomicAdd(dst + 2, acc.z); atomicAdd(dst + 3, acc.w);
        if (lane == 0) atomicAdd(&g_gcnt[curg], (float)cnt);
    }
}

// ---------------- output head: out = (gsum/cnt) @ W_out + b_out ----------------
__global__ __launch_bounds__(128) void out_kernel(const float* __restrict__ Wout,
                                                  const float* __restrict__ bout,
                                                  float* __restrict__ out) {
    __shared__ float row[128];
    int g = blockIdx.x, j = threadIdx.x;
    float cnt = fmaxf(g_gcnt[g], 1.0f);
    row[j] = g_gsum[(size_t)g * 128 + j] / cnt;
    __syncthreads();
    float acc = bout[j];
#pragma unroll 8
    for (int k = 0; k < 128; k++)
        acc = fmaf(row[k], Wout[(size_t)k * 128 + j], acc);
    out[(size_t)g * 128 + j] = acc;
}

// ---------------- launch ----------------
extern "C" void kernel_launch(void* const* d_in, const int* in_sizes, int n_in,
                              void* d_out, int out_size) {
    const float* x      = (const float*)d_in[0];
    const float* W_in   = (const float*)d_in[1];
    const float* b_in   = (const float*)d_in[2];
    const float* W_conv = (const float*)d_in[3];
    const float* b_conv = (const float*)d_in[4];
    const float* gamma  = (const float*)d_in[5];
    const float* beta   = (const float*)d_in[6];
    const float* W_out  = (const float*)d_in[7];
    const float* b_out  = (const float*)d_in[8];
    const void*  edge   = d_in[9];
    const void*  batch  = d_in[10];
    float* out = (float*)d_out;

    // idempotent; safe under graph capture
    cudaFuncSetAttribute(gemm_kernel<0>, cudaFuncAttributeMaxDynamicSharedMemorySize, SM_TOT);
    cudaFuncSetAttribute(gemm_kernel<1>, cudaFuncAttributeMaxDynamicSharedMemorySize, SM_TOT);
    cudaFuncSetAttribute(gemm_kernel<2>, cudaFuncAttributeMaxDynamicSharedMemorySize, SM_TOT);

    const int GEMM_GRID = (NN + 127) / 128;            // 1563
    const int SCAN_GRID = (NN + 255) / 256;            // 782
    const int AGG_GRID  = 1563;                        // round-9 validated config
    const int POOL_GRID = (NN + 8 * POOL_C - 1) / (8 * POOL_C);

    detect_kernel<<<1, 1>>>(edge, batch);
    setup_kernel<<<(GG * HH + 255) / 256, 256>>>();
    deg_kernel<<<(EE + 255) / 256, 256>>>(edge);

    blocksum_kernel<<<SCAN_GRID, 256>>>();             // + dinv fused
    scanb_kernel<<<1, 1024>>>(SCAN_GRID);
    offsets_kernel<<<SCAN_GRID, 256>>>();
    fill_kernel<<<(EE + 255) / 256, 256>>>(edge);      // + nrm precompute

    wtprep_kernel<<<(4 * HH * HH + 255) / 256, 256>>>(W_in, W_conv);

    gemm_kernel<0><<<GEMM_GRID, 256, SM_TOT>>>(x, 0, b_in);

    for (int l = 0; l < LL; l++) {
        if (l == 0)
            gemm_kernel<1><<<GEMM_GRID, 256, SM_TOT>>>(nullptr, 1 + l, nullptr);
        else
            gemm_kernel<2><<<GEMM_GRID, 256, SM_TOT>>>(nullptr, 1 + l, nullptr);
        agg_kernel<<<AGG_GRID, 256>>>(b_conv + (size_t)l * HH);
        bn_finalize_kernel<<<1, 128>>>(gamma + (size_t)l * HH, beta + (size_t)l * HH);
    }

    pool_kernel<<<POOL_GRID, 256>>>(batch);   // applies layer-3 BN inline
    out_kernel<<<GG, 128>>>(W_out, b_out, out);
}

// round 13
// speedup vs baseline: 1.3065x; 1.0078x over previous
#include <cuda_runtime.h>
#include <cuda_bf16.h>
#include <cstdint>

#define NN 200000
#define EE 400000
#define HH 128
#define GG 4096
#define LL 3

// ---------------- scratch (static __device__, allocation-free) ----------------
__device__ __align__(16) float g_h [(size_t)NN * HH];   // node features (residual)
__device__ __align__(16) float g_m [(size_t)NN * HH];   // per-layer linear output
__device__ __align__(16) float g_hn[(size_t)NN * HH];   // aggregated messages
__device__ __align__(16) __nv_bfloat16 g_wthi[4 * HH * HH];  // W^T hi, [w][n][k]
__device__ __align__(16) __nv_bfloat16 g_wtlo[4 * HH * HH];  // W^T lo
__device__ float  g_deg[NN];
__device__ int    g_icnt[NN];
__device__ int    g_off[NN + 1];
__device__ int    g_cur[NN];
__device__ int    g_src[EE];
__device__ float  g_nrm[EE];                            // dinv[src]*dinv[dst] per CSR slot
__device__ int    g_bsum[1024];
__device__ int    g_boff[1024];
__device__ double g_sum[LL][HH];                        // per-layer BN stats (no reset needed)
__device__ double g_sumsq[LL][HH];
__device__ __align__(16) float g_gsum[(size_t)GG * HH];
__device__ float g_gcnt[GG];
__device__ int   g_idx64;
__device__ int   g_bidx64;

// ---------------- helpers ----------------
__device__ __forceinline__ void split_bf(float v, unsigned short& hi, unsigned short& lo) {
    __nv_bfloat16 h = __float2bfloat16(v);
    __nv_bfloat16 l = __float2bfloat16(v - __bfloat162float(h));
    hi = *(unsigned short*)&h;
    lo = *(unsigned short*)&l;
}
__device__ __forceinline__ uint32_t pack_us(unsigned short a, unsigned short b) {
    return (uint32_t)a | ((uint32_t)b << 16);
}
__device__ __forceinline__ void mma_bf16(float* d, const uint32_t* a, uint32_t b0, uint32_t b1) {
    asm volatile(
        "mma.sync.aligned.m16n8k16.row.col.f32.bf16.bf16.f32 "
        "{%0,%1,%2,%3}, {%4,%5,%6,%7}, {%8,%9}, {%0,%1,%2,%3};"
        : "+f"(d[0]), "+f"(d[1]), "+f"(d[2]), "+f"(d[3])
        : "r"(a[0]), "r"(a[1]), "r"(a[2]), "r"(a[3]), "r"(b0), "r"(b1));
}
// compute BN scale/shift for channel j of stat-row sr
__device__ __forceinline__ void bn_coef(int sr, int j, const float* gamma, const float* beta,
                                        float& sc, float& sh) {
    float mu  = (float)(g_sum[sr][j] / (double)NN);
    float var = (float)(g_sumsq[sr][j] / (double)NN) - mu * mu;
    float inv = rsqrtf(var + 1e-5f);
    sc = inv * gamma[j];
    sh = beta[j] - mu * sc;
}

// ---------------- index width detection (bounds-safe for both widths) ----------------
__global__ void detect_kernel(const void* edge, const void* batch) {
    const int* we = (const int*)edge;
    const int* wb = (const int*)batch;
    int nz_e = 0, nz_b = 0;
    for (int i = 0; i < 64; i++) {
        nz_e |= we[1 + 2 * (i * (EE / 64))];
        nz_b |= wb[(NN - 1) - 2 * i];
    }
    g_idx64  = (nz_e == 0) ? 1 : 0;
    g_bidx64 = (nz_b == 0) ? 1 : 0;
}
__device__ __forceinline__ int ld_eidx(const void* p, int i) {
    return g_idx64 ? (int)((const long long*)p)[i] : ((const int*)p)[i];
}
__device__ __forceinline__ int ld_bidx(const void* p, int i) {
    return g_bidx64 ? (int)((const long long*)p)[i] : ((const int*)p)[i];
}

// ---------------- setup / degree / CSR ----------------
__global__ void setup_kernel() {
    int i = blockIdx.x * blockDim.x + threadIdx.x;
    if (i < NN) { g_icnt[i] = 0; g_cur[i] = 0; }
    if (i < GG * HH) g_gsum[i] = 0.0f;
    if (i < GG) g_gcnt[i] = 0.0f;
    if (i < LL * HH) { ((double*)g_sum)[i] = 0.0; ((double*)g_sumsq)[i] = 0.0; }
}
__global__ void deg_kernel(const void* edge) {
    int e = blockIdx.x * blockDim.x + threadIdx.x;
    if (e < EE) atomicAdd(&g_icnt[ld_eidx(edge, EE + e)], 1);
}
// blocksum + dinv fused
__global__ __launch_bounds__(256) void blocksum_kernel() {
    __shared__ int sm[256];
    int t = threadIdx.x, i = blockIdx.x * 256 + t;
    int c = (i < NN) ? g_icnt[i] : 0;
    if (i < NN) g_deg[i] = rsqrtf((float)(c + 1));
    sm[t] = c;
    __syncthreads();
    for (int d = 128; d > 0; d >>= 1) { if (t < d) sm[t] += sm[t + d]; __syncthreads(); }
    if (t == 0) g_bsum[blockIdx.x] = sm[0];
}
__global__ __launch_bounds__(1024) void scanb_kernel(int nblocks) {
    __shared__ int sm[1024];
    int t = threadIdx.x;
    int v = (t < nblocks) ? g_bsum[t] : 0;
    sm[t] = v;
    __syncthreads();
    for (int d = 1; d < 1024; d <<= 1) {
        int add = (t >= d) ? sm[t - d] : 0;
        __syncthreads(); sm[t] += add; __syncthreads();
    }
    g_boff[t] = sm[t] - v;
}
__global__ __launch_bounds__(256) void offsets_kernel() {
    __shared__ int sm[256];
    int t = threadIdx.x, i = blockIdx.x * 256 + t;
    int c = (i < NN) ? g_icnt[i] : 0;
    sm[t] = c;
    __syncthreads();
    for (int d = 1; d < 256; d <<= 1) {
        int add = (t >= d) ? sm[t - d] : 0;
        __syncthreads(); sm[t] += add; __syncthreads();
    }
    int off = g_boff[blockIdx.x] + sm[t] - c;
    if (i < NN) g_off[i] = off;
    if (i == NN - 1) g_off[NN] = off + c;
}
__global__ __launch_bounds__(256) void fill_kernel(const void* __restrict__ edge) {
    int e = blockIdx.x * blockDim.x + threadIdx.x;
    if (e >= EE) return;
    int r = ld_eidx(edge, e);
    int c = ld_eidx(edge, EE + e);
    int pos = atomicAdd(&g_cur[c], 1);
    int slot = g_off[c] + pos;
    g_src[slot] = r;
    g_nrm[slot] = g_deg[r] * g_deg[c];
}

// ---------------- weight prep: W^T split to bf16 hi/lo ----------------
__global__ __launch_bounds__(256) void wtprep_kernel(const float* __restrict__ W_in,
                                                     const float* __restrict__ W_conv) {
    int idx = blockIdx.x * blockDim.x + threadIdx.x;   // 4*16384
    if (idx >= 4 * HH * HH) return;
    int w = idx >> 14, r = idx & 16383;
    int n = r >> 7, k = r & 127;
    const float* W = (w == 0) ? W_in : (W_conv + (size_t)(w - 1) * HH * HH);
    unsigned short hi, lo;
    split_bf(W[(size_t)k * HH + n], hi, lo);
    ((unsigned short*)g_wthi)[idx] = hi;
    ((unsigned short*)g_wtlo)[idx] = lo;
}

// ---------------- tensor-core GEMM via mma.sync bf16 split ----------------
// C[n][j] = sum_k A[n][k] * W[k][j]  with A = x (MODE 0) or g_h (MODE 1/2).
// MODE 0: g_h = C + bias
// MODE 1: g_m = C
// MODE 2: A = g_h + relu(g_hn*sc+sh) (sc/sh computed inline from stats), g_m = C
#define KS 136                                 // padded row stride (bf16 elems)
#define SM_AHI 0
#define SM_ALO (128 * KS * 2)
#define SM_BHI (2 * 128 * KS * 2)
#define SM_BLO (3 * 128 * KS * 2)
#define SM_SC  (4 * 128 * KS * 2)              // 128 floats
#define SM_SH  (SM_SC + 512)
#define SM_TOT (SM_SH + 512)                   // 140288 bytes

template <int MODE>
__global__ __launch_bounds__(256, 1) void gemm_kernel(
    const float* __restrict__ Ain, int widx, const float* __restrict__ bias,
    const float* __restrict__ gamma, const float* __restrict__ beta, int statrow)
{
    extern __shared__ char smem[];
    const unsigned short* Whi = (const unsigned short*)g_wthi + (size_t)widx * HH * HH;
    const unsigned short* Wlo = (const unsigned short*)g_wtlo + (size_t)widx * HH * HH;
    float* s_sc = (float*)(smem + SM_SC);
    float* s_sh = (float*)(smem + SM_SH);

    int tid  = threadIdx.x;
    int n0   = blockIdx.x * 128;
    int lane = tid & 31;
    int wid  = tid >> 5;
    int gid  = lane >> 2;          // 0..7
    int tg   = lane & 3;           // 0..3
    int m_base = (wid >> 1) * 32;  // warp row base within tile
    int n_base = (wid & 1) * 64;   // warp col base within tile

    if (MODE == 2) {
        if (tid < 128) {
            float sc, sh;
            bn_coef(statrow, tid, gamma, beta, sc, sh);
            s_sc[tid] = sc; s_sh[tid] = sh;
        }
        __syncthreads();
    }

    // ---- stage A (split fp32 -> bf16 hi/lo), optionally fused BN-apply ----
    for (int t = 0; t < 16; t++) {
        int idx = tid + t * 256;               // 4096 float4 slots
        int r   = idx >> 5;                    // tile row
        int c4  = idx & 31;                    // float4 index in row
        int col = c4 * 4;
        int n   = n0 + r;
        float4 v = make_float4(0.f, 0.f, 0.f, 0.f);
        if (n < NN) {
            if (MODE == 0) {
                v = *(const float4*)(Ain + (size_t)n * 128 + col);
            } else if (MODE == 1) {
                v = *(const float4*)(g_h + (size_t)n * 128 + col);
            } else {
                float4 h  = *(const float4*)(g_h  + (size_t)n * 128 + col);
                float4 hn = *(const float4*)(g_hn + (size_t)n * 128 + col);
                float4 sc = *(const float4*)(s_sc + col);
                float4 sh = *(const float4*)(s_sh + col);
                v.x = h.x + fmaxf(hn.x * sc.x + sh.x, 0.f);
                v.y = h.y + fmaxf(hn.y * sc.y + sh.y, 0.f);
                v.z = h.z + fmaxf(hn.z * sc.z + sh.z, 0.f);
                v.w = h.w + fmaxf(hn.w * sc.w + sh.w, 0.f);
                *(float4*)(g_h + (size_t)n * 128 + col) = v;   // row owned by this block
            }
        }
        unsigned short h0, h1, h2, h3, l0, l1, l2, l3;
        split_bf(v.x, h0, l0); split_bf(v.y, h1, l1);
        split_bf(v.z, h2, l2); split_bf(v.w, h3, l3);
        uint32_t off = (uint32_t)r * (KS * 2) + col * 2;
        *(uint32_t*)(smem + SM_AHI + off)     = pack_us(h0, h1);
        *(uint32_t*)(smem + SM_AHI + off + 4) = pack_us(h2, h3);
        *(uint32_t*)(smem + SM_ALO + off)     = pack_us(l0, l1);
        *(uint32_t*)(smem + SM_ALO + off + 4) = pack_us(l2, l3);
    }
    // ---- stage B = W^T hi/lo (bf16, [n][k]) ----
    for (int t = 0; t < 8; t++) {
        int idx = tid + t * 256;               // 2048 uint4 slots
        int r = idx >> 4, q = idx & 15;        // row n, 8-bf16 chunk
        uint32_t off = (uint32_t)r * (KS * 2) + q * 16;
        *(uint4*)(smem + SM_BHI + off) = *(const uint4*)(Whi + (size_t)r * 128 + q * 8);
        *(uint4*)(smem + SM_BLO + off) = *(const uint4*)(Wlo + (size_t)r * 128 + q * 8);
    }
    __syncthreads();

    // ---- compute: 2 m-frags x 8 n-frags of m16n8, K = 8 steps of 16 ----
    float acc[2][8][4];
#pragma unroll
    for (int f = 0; f < 2; f++)
#pragma unroll
        for (int j = 0; j < 8; j++)
#pragma unroll
            for (int c = 0; c < 4; c++) acc[f][j][c] = 0.f;

#pragma unroll
    for (int ks = 0; ks < 8; ks++) {
        int k0 = ks * 16;
        uint32_t ahi[2][4], alo[2][4];
#pragma unroll
        for (int f = 0; f < 2; f++) {
            uint32_t r0 = (uint32_t)(m_base + f * 16 + gid) * (KS * 2);
            uint32_t r1 = r0 + 8 * (KS * 2);
            uint32_t cA = (uint32_t)(k0 + 2 * tg) * 2;
            ahi[f][0] = *(const uint32_t*)(smem + SM_AHI + r0 + cA);
            ahi[f][1] = *(const uint32_t*)(smem + SM_AHI + r1 + cA);
            ahi[f][2] = *(const uint32_t*)(smem + SM_AHI + r0 + cA + 16);
            ahi[f][3] = *(const uint32_t*)(smem + SM_AHI + r1 + cA + 16);
            alo[f][0] = *(const uint32_t*)(smem + SM_ALO + r0 + cA);
            alo[f][1] = *(const uint32_t*)(smem + SM_ALO + r1 + cA);
            alo[f][2] = *(const uint32_t*)(smem + SM_ALO + r0 + cA + 16);
            alo[f][3] = *(const uint32_t*)(smem + SM_ALO + r1 + cA + 16);
        }
#pragma unroll
        for (int j = 0; j < 8; j++) {
            uint32_t rn = (uint32_t)(n_base + j * 8 + gid) * (KS * 2);
            uint32_t cB = (uint32_t)(k0 + 2 * tg) * 2;
            uint32_t bh0 = *(const uint32_t*)(smem + SM_BHI + rn + cB);
            uint32_t bh1 = *(const uint32_t*)(smem + SM_BHI + rn + cB + 16);
            uint32_t bl0 = *(const uint32_t*)(smem + SM_BLO + rn + cB);
            uint32_t bl1 = *(const uint32_t*)(smem + SM_BLO + rn + cB + 16);
#pragma unroll
            for (int f = 0; f < 2; f++) {
                mma_bf16(acc[f][j], ahi[f], bh0, bh1);
                mma_bf16(acc[f][j], ahi[f], bl0, bl1);
                mma_bf16(acc[f][j], alo[f], bh0, bh1);
            }
        }
    }

    // ---- epilogue: direct float2 stores ----
#pragma unroll
    for (int f = 0; f < 2; f++) {
        int r0 = n0 + m_base + f * 16 + gid;
        int r1 = r0 + 8;
#pragma unroll
        for (int j = 0; j < 8; j++) {
            int col = n_base + j * 8 + 2 * tg;
            if (MODE == 0) {
                float bx = bias[col], by = bias[col + 1];
                if (r0 < NN) *(float2*)(g_h + (size_t)r0 * 128 + col) =
                    make_float2(acc[f][j][0] + bx, acc[f][j][1] + by);
                if (r1 < NN) *(float2*)(g_h + (size_t)r1 * 128 + col) =
                    make_float2(acc[f][j][2] + bx, acc[f][j][3] + by);
            } else {
                if (r0 < NN) *(float2*)(g_m + (size_t)r0 * 128 + col) =
                    make_float2(acc[f][j][0], acc[f][j][1]);
                if (r1 < NN) *(float2*)(g_m + (size_t)r1 * 128 + col) =
                    make_float2(acc[f][j][2], acc[f][j][3]);
            }
        }
    }
}

// ---------------- aggregation (CSR gather) + fused BN statistics ----------------
// hn[n] = bias + m[n]*dinv[n]^2 + sum_e m[src_e]*nrm_e ; stats into layer row l.
__global__ __launch_bounds__(256) void agg_kernel(const float* __restrict__ bias, int l) {
    int lane = threadIdx.x & 31;
    int w    = threadIdx.x >> 5;
    float4 b4 = ((const float4*)bias)[lane];

    float s0 = 0.f, s1 = 0.f, s2 = 0.f, s3 = 0.f;
    float q0 = 0.f, q1 = 0.f, q2 = 0.f, q3 = 0.f;

    for (int n = blockIdx.x * 8 + w; n < NN; n += gridDim.x * 8) {
        float dc = g_deg[n];
        float d2 = dc * dc;
        float4 m = ((const float4*)(g_m + (size_t)n * 128))[lane];
        float4 acc;
        acc.x = b4.x + m.x * d2;
        acc.y = b4.y + m.y * d2;
        acc.z = b4.z + m.z * d2;
        acc.w = b4.w + m.w * d2;

        int beg = g_off[n], end = g_off[n + 1];
        int i = beg;
        for (; i + 2 <= end; i += 2) {          // unrolled: 2 independent gathers
            int   r0  = g_src[i];
            int   r1  = g_src[i + 1];
            float nr0 = g_nrm[i];
            float nr1 = g_nrm[i + 1];
            float4 v0 = ((const float4*)(g_m + (size_t)r0 * 128))[lane];
            float4 v1 = ((const float4*)(g_m + (size_t)r1 * 128))[lane];
            acc.x += v0.x * nr0 + v1.x * nr1;
            acc.y += v0.y * nr0 + v1.y * nr1;
            acc.z += v0.z * nr0 + v1.z * nr1;
            acc.w += v0.w * nr0 + v1.w * nr1;
        }
        if (i < end) {
            int   r0  = g_src[i];
            float nr0 = g_nrm[i];
            float4 v0 = ((const float4*)(g_m + (size_t)r0 * 128))[lane];
            acc.x += v0.x * nr0; acc.y += v0.y * nr0;
            acc.z += v0.z * nr0; acc.w += v0.w * nr0;
        }
        ((float4*)(g_hn + (size_t)n * 128))[lane] = acc;

        s0 += acc.x; q0 += acc.x * acc.x;
        s1 += acc.y; q1 += acc.y * acc.y;
        s2 += acc.z; q2 += acc.z * acc.z;
        s3 += acc.w; q3 += acc.w * acc.w;
    }

    __shared__ float sb[2][8][128];
    int ch = lane * 4;
    sb[0][w][ch + 0] = s0; sb[0][w][ch + 1] = s1;
    sb[0][w][ch + 2] = s2; sb[0][w][ch + 3] = s3;
    sb[1][w][ch + 0] = q0; sb[1][w][ch + 1] = q1;
    sb[1][w][ch + 2] = q2; sb[1][w][ch + 3] = q3;
    __syncthreads();

    int t = threadIdx.x;
    if (t < 128) {
        float a = 0.f;
#pragma unroll
        for (int ww = 0; ww < 8; ww++) a += sb[0][ww][t];
        atomicAdd(&g_sum[l][t], (double)a);
    } else {
        int tc = t - 128;
        float a = 0.f;
#pragma unroll
        for (int ww = 0; ww < 8; ww++) a += sb[1][ww][tc];
        atomicAdd(&g_sumsq[l][tc], (double)a);
    }
}

// ---------------- pool with fused final BN (coef computed inline; batch sorted) ----------------
#define POOL_C 64
__global__ __launch_bounds__(256) void pool_kernel(const void* __restrict__ batch,
                                                   const float* __restrict__ gamma,
                                                   const float* __restrict__ beta) {
    __shared__ float s_sc[128], s_sh[128];
    int tid  = threadIdx.x;
    int lane = tid & 31;
    int w    = tid >> 5;
    if (tid < 128) {
        float sc, sh;
        bn_coef(LL - 1, tid, gamma, beta, sc, sh);
        s_sc[tid] = sc; s_sh[tid] = sh;
    }
    __syncthreads();

    int n0 = (blockIdx.x * 8 + w) * POOL_C;
    if (n0 >= NN) return;
    int nend = n0 + POOL_C;
    if (nend > NN) nend = NN;

    float4 sc = ((const float4*)s_sc)[lane];
    float4 sh = ((const float4*)s_sh)[lane];

    float4 acc = make_float4(0.f, 0.f, 0.f, 0.f);
    int curg = -1, cnt = 0;

    for (int n = n0; n < nend; n++) {
        int g = ld_bidx(batch, n);
        if (g != curg) {
            if (curg >= 0) {
                float* dst = g_gsum + (size_t)curg * 128 + lane * 4;
                atomicAdd(dst + 0, acc.x); atomicAdd(dst + 1, acc.y);
                atomicAdd(dst + 2, acc.z); atomicAdd(dst + 3, acc.w);
                if (lane == 0) atomicAdd(&g_gcnt[curg], (float)cnt);
            }
            curg = g;
            acc = make_float4(0.f, 0.f, 0.f, 0.f);
            cnt = 0;
        }
        float4 h  = ((const float4*)(g_h  + (size_t)n * 128))[lane];
        float4 hn = ((const float4*)(g_hn + (size_t)n * 128))[lane];
        acc.x += h.x + fmaxf(hn.x * sc.x + sh.x, 0.f);
        acc.y += h.y + fmaxf(hn.y * sc.y + sh.y, 0.f);
        acc.z += h.z + fmaxf(hn.z * sc.z + sh.z, 0.f);
        acc.w += h.w + fmaxf(hn.w * sc.w + sh.w, 0.f);
        cnt++;
    }
    if (curg >= 0) {
        float* dst = g_gsum + (size_t)curg * 128 + lane * 4;
        atomicAdd(dst + 0, acc.x); atomicAdd(dst + 1, acc.y);
        atomicAdd(dst + 2, acc.z); atomicAdd(dst + 3, acc.w);
        if (lane == 0) atomicAdd(&g_gcnt[curg], (float)cnt);
    }
}

// ---------------- output head: out = (gsum/cnt) @ W_out + b_out ----------------
__global__ __launch_bounds__(128) void out_kernel(const float* __restrict__ Wout,
                                                  const float* __restrict__ bout,
                                                  float* __restrict__ out) {
    __shared__ float row[128];
    int g = blockIdx.x, j = threadIdx.x;
    float cnt = fmaxf(g_gcnt[g], 1.0f);
    row[j] = g_gsum[(size_t)g * 128 + j] / cnt;
    __syncthreads();
    float acc = bout[j];
#pragma unroll 8
    for (int k = 0; k < 128; k++)
        acc = fmaf(row[k], Wout[(size_t)k * 128 + j], acc);
    out[(size_t)g * 128 + j] = acc;
}

// ---------------- launch ----------------
extern "C" void kernel_launch(void* const* d_in, const int* in_sizes, int n_in,
                              void* d_out, int out_size) {
    const float* x      = (const float*)d_in[0];
    const float* W_in   = (const float*)d_in[1];
    const float* b_in   = (const float*)d_in[2];
    const float* W_conv = (const float*)d_in[3];
    const float* b_conv = (const float*)d_in[4];
    const float* gamma  = (const float*)d_in[5];
    const float* beta   = (const float*)d_in[6];
    const float* W_out  = (const float*)d_in[7];
    const float* b_out  = (const float*)d_in[8];
    const void*  edge   = d_in[9];
    const void*  batch  = d_in[10];
    float* out = (float*)d_out;

    // idempotent; safe under graph capture
    cudaFuncSetAttribute(gemm_kernel<0>, cudaFuncAttributeMaxDynamicSharedMemorySize, SM_TOT);
    cudaFuncSetAttribute(gemm_kernel<1>, cudaFuncAttributeMaxDynamicSharedMemorySize, SM_TOT);
    cudaFuncSetAttribute(gemm_kernel<2>, cudaFuncAttributeMaxDynamicSharedMemorySize, SM_TOT);

    const int GEMM_GRID = (NN + 127) / 128;            // 1563
    const int SCAN_GRID = (NN + 255) / 256;            // 782
    const int AGG_GRID  = 1563;                        // validated config
    const int POOL_GRID = (NN + 8 * POOL_C - 1) / (8 * POOL_C);

    detect_kernel<<<1, 1>>>(edge, batch);
    setup_kernel<<<(GG * HH + 255) / 256, 256>>>();
    deg_kernel<<<(EE + 255) / 256, 256>>>(edge);

    blocksum_kernel<<<SCAN_GRID, 256>>>();             // + dinv fused
    scanb_kernel<<<1, 1024>>>(SCAN_GRID);
    offsets_kernel<<<SCAN_GRID, 256>>>();
    fill_kernel<<<(EE + 255) / 256, 256>>>(edge);      // + nrm precompute

    wtprep_kernel<<<(4 * HH * HH + 255) / 256, 256>>>(W_in, W_conv);

    gemm_kernel<0><<<GEMM_GRID, 256, SM_TOT>>>(x, 0, b_in, nullptr, nullptr, 0);

    for (int l = 0; l < LL; l++) {
        if (l == 0)
            gemm_kernel<1><<<GEMM_GRID, 256, SM_TOT>>>(nullptr, 1 + l, nullptr,
                                                       nullptr, nullptr, 0);
        else
            gemm_kernel<2><<<GEMM_GRID, 256, SM_TOT>>>(nullptr, 1 + l, nullptr,
                                                       gamma + (size_t)(l - 1) * HH,
                                                       beta  + (size_t)(l - 1) * HH,
                                                       l - 1);
        agg_kernel<<<AGG_GRID, 256>>>(b_conv + (size_t)l * HH, l);
    }

    pool_kernel<<<POOL_GRID, 256>>>(batch,
                                    gamma + (size_t)(LL - 1) * HH,
                                    beta  + (size_t)(LL - 1) * HH);
    out_kernel<<<GG, 128>>>(W_out, b_out, out);
}